// round 16
// baseline (speedup 1.0000x reference)
#include <cuda_runtime.h>
#include <cuda_fp16.h>
#include <cstdint>

typedef unsigned long long ull;

// ---------------- scratch (device globals; no allocation allowed) ----------------
__device__ float  g_Wp[192 * 128];                      // permutation-adjusted W
__device__ __half g_Tu[(size_t)500000 * 128];           // user table  (128 MB, fp16)
__device__ __half g_Ti[(size_t)100000 * 128];           // item table  (25.6 MB, fp16)
__device__ int    g_is64;                               // adj dtype flag
__device__ int    g_swap;                               // adjA/adjB swap flag

// ---------------- threefry2x32 core ----------------
__device__ __forceinline__ unsigned rotl32(unsigned x, int d) {
    return (x << d) | (x >> (32 - d));
}

__device__ void threefry2x32(unsigned k0, unsigned k1, unsigned& x0, unsigned& x1) {
    unsigned k2 = k0 ^ k1 ^ 0x1BD11BDAu;
    x0 += k0; x1 += k1;
    const int R0[4] = {13, 15, 26, 6};
    const int R1[4] = {17, 29, 16, 24};
#pragma unroll
    for (int i = 0; i < 4; i++) { x0 += x1; x1 = rotl32(x1, R0[i]); x1 ^= x0; }
    x0 += k1; x1 += k2 + 1u;
#pragma unroll
    for (int i = 0; i < 4; i++) { x0 += x1; x1 = rotl32(x1, R1[i]); x1 ^= x0; }
    x0 += k2; x1 += k0 + 2u;
#pragma unroll
    for (int i = 0; i < 4; i++) { x0 += x1; x1 = rotl32(x1, R0[i]); x1 ^= x0; }
    x0 += k0; x1 += k1 + 3u;
#pragma unroll
    for (int i = 0; i < 4; i++) { x0 += x1; x1 = rotl32(x1, R1[i]); x1 ^= x0; }
    x0 += k1; x1 += k2 + 4u;
#pragma unroll
    for (int i = 0; i < 4; i++) { x0 += x1; x1 = rotl32(x1, R0[i]); x1 ^= x0; }
    x0 += k2; x1 += k0 + 5u;
}

// ---------------- K0: jax PARTITIONABLE threefry -> reordered W, + probes -------
// 1024 threads: parallel dtype/swap probes (measured 10.4us).
__global__ void k_build_wp(const float* __restrict__ W,
                           const void* __restrict__ adjA) {
    __shared__ unsigned bits[2][64];
    __shared__ unsigned subk[2][2];
    __shared__ int src[192];
    __shared__ int s_all0, s_big;
    const int t = threadIdx.x;
    const int s = (t < 128) ? (t >> 6) : -1;   // seed group: 0->42, 1->43
    const int i = t & 63;

    if (t < 192) src[t] = t;                   // review block stays identity
    if (t == 0) { s_all0 = 1; s_big = 0; }

    if (t < 2) {                               // foldlike split: subkey = TF(key,(0,1))
        unsigned x0 = 0u, x1 = 1u;
        threefry2x32(0u, 42u + (unsigned)t, x0, x1);
        subk[t][0] = x0; subk[t][1] = x1;
    }
    __syncthreads();

    if (t < 64) {
        if (((const int*)adjA)[2 * t + 1] != 0) atomicAnd(&s_all0, 0);
    }
    __syncthreads();
    const int is64 = s_all0;

    {
        int big = 0;
        if (is64) {
            const long long* a = (const long long*)adjA;
#pragma unroll
            for (int j = 0; j < 4; j++) big |= (a[t * 4 + j] >= 100000);
        } else {
            const int* a = (const int*)adjA;
#pragma unroll
            for (int j = 0; j < 4; j++) big |= (a[t * 4 + j] >= 100000);
        }
        if (big) s_big = 1;                    // race-benign
    }

    if (s >= 0) {   // partitionable random_bits: counter (0, i), output x0^x1
        unsigned x0 = 0u, x1 = (unsigned)i;
        threefry2x32(subk[s][0], subk[s][1], x0, x1);
        bits[s][i] = x0 ^ x1;
    }
    __syncthreads();

    if (t == 0) { g_is64 = is64; g_swap = !s_big; }

    if (s >= 0) {   // stable rank; Wp[block+i] = W[block+rank_i]
        unsigned kv = bits[s][i];
        int r = 0;
        for (int j = 0; j < 64; j++) {
            unsigned kj = bits[s][j];
            r += (kj < kv) || (kj == kv && j < i);
        }
        src[(s + 1) * 64 + i] = (s + 1) * 64 + r;
    }
    __syncthreads();

    for (int idx = t; idx < 192 * 128; idx += blockDim.x)
        g_Wp[idx] = W[src[idx >> 7] * 128 + (idx & 127)];
}

// ---------------- packed f32x2 helpers ----------------
__device__ __forceinline__ ull pk2(float x, float y) {
    ull r; asm("mov.b64 %0, {%1, %2};" : "=l"(r) : "f"(x), "f"(y)); return r;
}
__device__ __forceinline__ float2 upk2(ull v) {
    float2 f; asm("mov.b64 {%0, %1}, %2;" : "=f"(f.x), "=f"(f.y) : "l"(v)); return f;
}
__device__ __forceinline__ ull fma2_(ull a, ull b, ull c) {
    ull d; asm("fma.rn.f32x2 %0, %1, %2, %3;" : "=l"(d) : "l"(a), "l"(b), "l"(c)); return d;
}
__device__ __forceinline__ void pf_l2(const void* p) {
    asm volatile("prefetch.global.L2 [%0];" :: "l"(p));
}

// smem layout
constexpr int OF_BS  = 0;                 // 64*128 floats  = 32 KB
constexpr int OF_AT0 = 32768;             // 16 KB
constexpr int OF_AT1 = 49152;             // 16 KB
constexpr int OF_IDX = 65536;             // 2 tiles x (128 au + 128 ai) = 2 KB
constexpr int SMEM_DYN = 67584;

// ---------------- pipeline building blocks ----------------
__device__ __forceinline__ void load_chunk(const float4* A4, int M, int row0,
                                           int half, int t, float4 v[4]) {
#pragma unroll
    for (int it = 0; it < 4; it++) {
        int q = it * 256 + t;
        int gr = min(row0 + (q >> 3), M - 1);
        v[it] = A4[(size_t)gr * 16 + half * 8 + (q & 7)];
    }
}

__device__ __forceinline__ void store_chunk(float* At, int t, const float4 v[4]) {
#pragma unroll
    for (int it = 0; it < 4; it++) {
        int q = it * 256 + t;
        int r = q >> 3, kc4 = q & 7;
        int pr = r ^ (4 * kc4);
        float* dst = At + (kc4 * 4) * 128 + pr;
        dst[0] = v[it].x; dst[128] = v[it].y; dst[256] = v[it].z; dst[384] = v[it].w;
    }
}

__device__ __forceinline__ void compute_chunk(const float* At, const float* Bs32,
                                              int row_w, int ty, int c0, ull acc[8][4]) {
#pragma unroll 4
    for (int kk = 0; kk < 32; kk++) {
        int vv = kk & 28;
        const float* pa = At + kk * 128 + row_w + ((4 * ty) ^ vv);
        float4 a0 = *(const float4*)pa;
        float4 a1 = *(const float4*)(pa + 32);
        const float* pb = Bs32 + kk * 128 + c0;
        ulonglong2 bA = *(const ulonglong2*)(pb);
        ulonglong2 bB = *(const ulonglong2*)(pb + 4);
#pragma unroll
        for (int i = 0; i < 8; i++) {
            float av = (i == 0) ? a0.x : (i == 1) ? a0.y : (i == 2) ? a0.z
                     : (i == 3) ? a0.w : (i == 4) ? a1.x : (i == 5) ? a1.y
                     : (i == 6) ? a1.z : a1.w;
            ull ad = pk2(av, av);
            acc[i][0] = fma2_(ad, bA.x, acc[i][0]);
            acc[i][1] = fma2_(ad, bA.y, acc[i][1]);
            acc[i][2] = fma2_(ad, bB.x, acc[i][2]);
            acc[i][3] = fma2_(ad, bB.y, acc[i][3]);
        }
    }
}

__device__ __forceinline__ void copy_B(char* smem, int koff, int t) {
    const float4* w4 = (const float4*)(g_Wp + koff * 128);
    float4* b4 = (float4*)(smem + OF_BS);
#pragma unroll
    for (int i = 0; i < 8; i++) b4[i * 256 + t] = w4[i * 256 + t];
}

__device__ __forceinline__ void zero_acc(ull acc[8][4]) {
#pragma unroll
    for (int i = 0; i < 8; i++)
#pragma unroll
        for (int j = 0; j < 4; j++) acc[i][j] = 0ull;
}

// ---------------- table builder: tile-pair per CTA, B loaded once ----------------
__global__ __launch_bounds__(256, 2)
void k_tables(const float* __restrict__ item, int n_i, int nbi, int Gib,
              const float* __restrict__ user, int n_u, int nbu) {
    extern __shared__ __align__(16) char smem[];
    float* Bs  = (float*)(smem + OF_BS);
    float* At0 = (float*)(smem + OF_AT0);
    float* At1 = (float*)(smem + OF_AT1);

    const int t = threadIdx.x;
    const int w = t >> 5, l = t & 31;
    const int tx = l & 3, ty = l >> 2;
    const int row_w = (w & 1) * 64;
    const int c0 = (w >> 1) * 32 + tx * 8;
    const int rA = row_w + 4 * ty;

    const bool is_item = (int)blockIdx.x < Gib;
    const float* A = is_item ? item : user;
    const int M = is_item ? n_i : n_u;
    const int ntl = is_item ? nbi : nbu;
    const int b = is_item ? blockIdx.x : blockIdx.x - Gib;
    const int koff = is_item ? 128 : 64;
    __half* T = is_item ? g_Ti : g_Tu;

    const int tile0 = b * 2;
    const int tile1 = min(tile0 + 1, ntl - 1);
    const int r0a = tile0 * 128, r0b = tile1 * 128;
    const float4* A4 = (const float4*)A;

    auto epi = [&](ull acc[8][4], int row0) {
#pragma unroll
        for (int i = 0; i < 8; i++) {
            int lr = rA + (i & 3) + (i >> 2) * 32;
            int gr = row0 + lr;
            if (gr >= M) continue;
            __half2 h0 = __float22half2_rn(upk2(acc[i][0]));
            __half2 h1 = __float22half2_rn(upk2(acc[i][1]));
            __half2 h2 = __float22half2_rn(upk2(acc[i][2]));
            __half2 h3 = __float22half2_rn(upk2(acc[i][3]));
            uint4 pk;
            pk.x = *(unsigned*)&h0; pk.y = *(unsigned*)&h1;
            pk.z = *(unsigned*)&h2; pk.w = *(unsigned*)&h3;
            *(uint4*)(T + ((size_t)gr << 7) + c0) = pk;
        }
    };

    float4 v[4];
    ull acc[8][4];

    load_chunk(A4, M, r0a, 0, t, v);
    copy_B(smem, koff, t);
    store_chunk(At0, t, v);
    __syncthreads();

    load_chunk(A4, M, r0a, 1, t, v);
    zero_acc(acc);
    compute_chunk(At0, Bs, row_w, ty, c0, acc);
    store_chunk(At1, t, v);
    __syncthreads();                       // A

    load_chunk(A4, M, r0b, 0, t, v);
    compute_chunk(At1, Bs + 32 * 128, row_w, ty, c0, acc);
    store_chunk(At0, t, v);
    epi(acc, r0a);
    __syncthreads();                       // B

    load_chunk(A4, M, r0b, 1, t, v);
    zero_acc(acc);
    compute_chunk(At0, Bs, row_w, ty, c0, acc);
    store_chunk(At1, t, v);
    __syncthreads();                       // C

    compute_chunk(At1, Bs + 32 * 128, row_w, ty, c0, acc);
    epi(acc, r0b);
}

// ---------------- review GEMM + gather + relu: tile-pair per CTA ----------------
__global__ __launch_bounds__(256, 2)
void k_review(const float* __restrict__ A, int M, int ntiles, float* __restrict__ Cout,
              const void* __restrict__ adjA, const void* __restrict__ adjB) {
    extern __shared__ __align__(16) char smem[];
    float* Bs  = (float*)(smem + OF_BS);
    float* At0 = (float*)(smem + OF_AT0);
    float* At1 = (float*)(smem + OF_AT1);
    int* sIdx  = (int*)(smem + OF_IDX);    // [2][256]: au[128], ai[128] per tile

    const int t = threadIdx.x;
    const int w = t >> 5, l = t & 31;
    const int tx = l & 3, ty = l >> 2;
    const int row_w = (w & 1) * 64;
    const int c0 = (w >> 1) * 32 + tx * 8;
    const int rA = row_w + 4 * ty;

    const int tile0 = blockIdx.x * 2;
    const int tile1 = min(tile0 + 1, ntiles - 1);
    const int r0a = tile0 * 128, r0b = tile1 * 128;

    const int is64 = g_is64;
    const void* aU = g_swap ? adjB : adjA;
    const void* aI = g_swap ? adjA : adjB;
    const float4* A4 = (const float4*)A;

    auto load_idx = [&](int row0, int* buf) {
        int lr = t & 127;
        int gr = min(row0 + lr, M - 1);
        if (t < 128) {
            int iu = is64 ? (int)((const long long*)aU)[gr] : ((const int*)aU)[gr];
            buf[lr] = iu;
            const char* p = (const char*)(g_Tu + ((size_t)iu << 7));
            pf_l2(p); pf_l2(p + 128);
        } else {
            int ii = is64 ? (int)((const long long*)aI)[gr] : ((const int*)aI)[gr];
            buf[128 + lr] = ii;
            const char* p = (const char*)(g_Ti + ((size_t)ii << 7));
            pf_l2(p); pf_l2(p + 128);
        }
    };

    auto epi = [&](ull acc[8][4], const int* au, const int* ai, int row0) {
#pragma unroll
        for (int h = 0; h < 2; h++) {
            uint4 gu[4], gi[4];
#pragma unroll
            for (int i = 0; i < 4; i++) {
                int lr = rA + i + h * 32;
                gu[i] = __ldg((const uint4*)(g_Tu + ((size_t)au[lr] << 7) + c0));
                gi[i] = __ldg((const uint4*)(g_Ti + ((size_t)ai[lr] << 7) + c0));
            }
#pragma unroll
            for (int i = 0; i < 4; i++) {
                int a = h * 4 + i;
                int gr = row0 + rA + i + h * 32;
                if (gr >= M) continue;
                float2 p0 = upk2(acc[a][0]), p1 = upk2(acc[a][1]);
                float2 p2 = upk2(acc[a][2]), p3 = upk2(acc[a][3]);
                float2 u0 = __half22float2(*(__half2*)&gu[i].x);
                float2 u1 = __half22float2(*(__half2*)&gu[i].y);
                float2 u2 = __half22float2(*(__half2*)&gu[i].z);
                float2 u3 = __half22float2(*(__half2*)&gu[i].w);
                float2 w0 = __half22float2(*(__half2*)&gi[i].x);
                float2 w1 = __half22float2(*(__half2*)&gi[i].y);
                float2 w2 = __half22float2(*(__half2*)&gi[i].z);
                float2 w3 = __half22float2(*(__half2*)&gi[i].w);
                float4 o0, o1;
                o0.x = fmaxf(p0.x + u0.x + w0.x, 0.f);
                o0.y = fmaxf(p0.y + u0.y + w0.y, 0.f);
                o0.z = fmaxf(p1.x + u1.x + w1.x, 0.f);
                o0.w = fmaxf(p1.y + u1.y + w1.y, 0.f);
                o1.x = fmaxf(p2.x + u2.x + w2.x, 0.f);
                o1.y = fmaxf(p2.y + u2.y + w2.y, 0.f);
                o1.z = fmaxf(p3.x + u3.x + w3.x, 0.f);
                o1.w = fmaxf(p3.y + u3.y + w3.y, 0.f);
                float4* dst = (float4*)(Cout + ((size_t)gr << 7) + c0);
                dst[0] = o0; dst[1] = o1;
            }
        }
    };

    float4 v[4];
    ull acc[8][4];

    load_idx(r0a, sIdx);
    load_idx(r0b, sIdx + 256);
    load_chunk(A4, M, r0a, 0, t, v);
    copy_B(smem, 0, t);
    store_chunk(At0, t, v);
    __syncthreads();

    load_chunk(A4, M, r0a, 1, t, v);
    zero_acc(acc);
    compute_chunk(At0, Bs, row_w, ty, c0, acc);
    store_chunk(At1, t, v);
    __syncthreads();                       // A

    load_chunk(A4, M, r0b, 0, t, v);
    compute_chunk(At1, Bs + 32 * 128, row_w, ty, c0, acc);
    store_chunk(At0, t, v);
    epi(acc, sIdx, sIdx + 128, r0a);
    __syncthreads();                       // B

    load_chunk(A4, M, r0b, 1, t, v);
    zero_acc(acc);
    compute_chunk(At0, Bs, row_w, ty, c0, acc);
    store_chunk(At1, t, v);
    __syncthreads();                       // C

    compute_chunk(At1, Bs + 32 * 128, row_w, ty, c0, acc);
    epi(acc, sIdx + 256, sIdx + 384, r0b);
}

// ---------------- launch ----------------
extern "C" void kernel_launch(void* const* d_in, const int* in_sizes, int n_in,
                              void* d_out, int out_size) {
    // classify inputs by element count (robust to metadata ordering)
    const float *review = nullptr, *user = nullptr, *item = nullptr, *W = nullptr;
    const void *adjA = nullptr, *adjB = nullptr;
    int n_r = 1000000, n_u = 500000, n_i = 100000;
    for (int k = 0; k < n_in; k++) {
        long long sz = in_sizes[k];
        if (sz == 64000000)      { review = (const float*)d_in[k]; n_r = (int)(sz / 64); }
        else if (sz == 32000000) { user   = (const float*)d_in[k]; n_u = (int)(sz / 64); }
        else if (sz == 6400000)  { item   = (const float*)d_in[k]; n_i = (int)(sz / 64); }
        else if (sz == 24576)    { W      = (const float*)d_in[k]; }
        else if (!adjA)          { adjA   = d_in[k]; }
        else                     { adjB   = d_in[k]; }
    }
    if (!review || !user || !item || !W || !adjA || !adjB) {
        review = (const float*)d_in[0]; user = (const float*)d_in[1];
        item   = (const float*)d_in[2]; W    = (const float*)d_in[3];
        adjA   = d_in[4];               adjB = d_in[5];
        n_r = in_sizes[0] / 64; n_u = in_sizes[1] / 64; n_i = in_sizes[2] / 64;
    }
    float* out = (float*)d_out;

    cudaFuncSetAttribute(k_tables, cudaFuncAttributeMaxDynamicSharedMemorySize, SMEM_DYN);
    cudaFuncSetAttribute(k_review, cudaFuncAttributeMaxDynamicSharedMemorySize, SMEM_DYN);

    int nbi = (n_i + 127) / 128;
    int nbu = (n_u + 127) / 128;
    int Gib = (nbi + 1) / 2;
    int Gub = (nbu + 1) / 2;
    int ntr = (n_r + 127) / 128;

    k_build_wp<<<1, 1024>>>(W, adjA);
    k_tables<<<Gib + Gub, 256, SMEM_DYN>>>(item, n_i, nbi, Gib, user, n_u, nbu);
    k_review<<<(ntr + 1) / 2, 256, SMEM_DYN>>>(review, n_r, ntr, out, adjA, adjB);
}

// round 17
// speedup vs baseline: 1.1953x; 1.1953x over previous
#include <cuda_runtime.h>
#include <cuda_fp16.h>
#include <cstdint>

typedef unsigned long long ull;

// ---------------- scratch (device globals; no allocation allowed) ----------------
__device__ float  g_Wp[192 * 128];                      // permutation-adjusted W
__device__ __half g_Tu[(size_t)500000 * 128];           // user table  (128 MB, fp16)
__device__ __half g_Ti[(size_t)100000 * 128];           // item table  (25.6 MB, fp16)
__device__ int    g_is64;                               // adj dtype flag
__device__ int    g_swap;                               // adjA/adjB swap flag

// ---------------- threefry2x32 core ----------------
__device__ __forceinline__ unsigned rotl32(unsigned x, int d) {
    return (x << d) | (x >> (32 - d));
}

__device__ void threefry2x32(unsigned k0, unsigned k1, unsigned& x0, unsigned& x1) {
    unsigned k2 = k0 ^ k1 ^ 0x1BD11BDAu;
    x0 += k0; x1 += k1;
    const int R0[4] = {13, 15, 26, 6};
    const int R1[4] = {17, 29, 16, 24};
#pragma unroll
    for (int i = 0; i < 4; i++) { x0 += x1; x1 = rotl32(x1, R0[i]); x1 ^= x0; }
    x0 += k1; x1 += k2 + 1u;
#pragma unroll
    for (int i = 0; i < 4; i++) { x0 += x1; x1 = rotl32(x1, R1[i]); x1 ^= x0; }
    x0 += k2; x1 += k0 + 2u;
#pragma unroll
    for (int i = 0; i < 4; i++) { x0 += x1; x1 = rotl32(x1, R0[i]); x1 ^= x0; }
    x0 += k0; x1 += k1 + 3u;
#pragma unroll
    for (int i = 0; i < 4; i++) { x0 += x1; x1 = rotl32(x1, R1[i]); x1 ^= x0; }
    x0 += k1; x1 += k2 + 4u;
#pragma unroll
    for (int i = 0; i < 4; i++) { x0 += x1; x1 = rotl32(x1, R0[i]); x1 ^= x0; }
    x0 += k2; x1 += k0 + 5u;
}

// ---------------- K0: jax PARTITIONABLE threefry -> reordered W, + probes -------
// 1024 threads: parallel dtype/swap probes (measured 10.4us).
__global__ void k_build_wp(const float* __restrict__ W,
                           const void* __restrict__ adjA) {
    __shared__ unsigned bits[2][64];
    __shared__ unsigned subk[2][2];
    __shared__ int src[192];
    __shared__ int s_all0, s_big;
    const int t = threadIdx.x;
    const int s = (t < 128) ? (t >> 6) : -1;   // seed group: 0->42, 1->43
    const int i = t & 63;

    if (t < 192) src[t] = t;                   // review block stays identity
    if (t == 0) { s_all0 = 1; s_big = 0; }

    if (t < 2) {                               // foldlike split: subkey = TF(key,(0,1))
        unsigned x0 = 0u, x1 = 1u;
        threefry2x32(0u, 42u + (unsigned)t, x0, x1);
        subk[t][0] = x0; subk[t][1] = x1;
    }
    __syncthreads();

    // int64 vs int32 probe (parallel): odd int32 slots of first 128 all zero => int64
    if (t < 64) {
        if (((const int*)adjA)[2 * t + 1] != 0) atomicAnd(&s_all0, 0);
    }
    __syncthreads();
    const int is64 = s_all0;

    // swap probe (parallel): any of first 4096 values >= 100000 => adjA is adj_u
    {
        int big = 0;
        if (is64) {
            const long long* a = (const long long*)adjA;
#pragma unroll
            for (int j = 0; j < 4; j++) big |= (a[t * 4 + j] >= 100000);
        } else {
            const int* a = (const int*)adjA;
#pragma unroll
            for (int j = 0; j < 4; j++) big |= (a[t * 4 + j] >= 100000);
        }
        if (big) s_big = 1;                    // race-benign
    }

    if (s >= 0) {   // partitionable random_bits: counter (0, i), output x0^x1
        unsigned x0 = 0u, x1 = (unsigned)i;
        threefry2x32(subk[s][0], subk[s][1], x0, x1);
        bits[s][i] = x0 ^ x1;
    }
    __syncthreads();

    if (t == 0) { g_is64 = is64; g_swap = !s_big; }

    if (s >= 0) {   // stable rank; Wp[block+i] = W[block+rank_i]
        unsigned kv = bits[s][i];
        int r = 0;
        for (int j = 0; j < 64; j++) {
            unsigned kj = bits[s][j];
            r += (kj < kv) || (kj == kv && j < i);
        }
        src[(s + 1) * 64 + i] = (s + 1) * 64 + r;
    }
    __syncthreads();

    for (int idx = t; idx < 192 * 128; idx += blockDim.x)
        g_Wp[idx] = W[src[idx >> 7] * 128 + (idx & 127)];
}

// ---------------- packed f32x2 helpers ----------------
__device__ __forceinline__ ull pk2(float x, float y) {
    ull r; asm("mov.b64 %0, {%1, %2};" : "=l"(r) : "f"(x), "f"(y)); return r;
}
__device__ __forceinline__ float2 upk2(ull v) {
    float2 f; asm("mov.b64 {%0, %1}, %2;" : "=f"(f.x), "=f"(f.y) : "l"(v)); return f;
}
__device__ __forceinline__ ull fma2_(ull a, ull b, ull c) {
    ull d; asm("fma.rn.f32x2 %0, %1, %2, %3;" : "=l"(d) : "l"(a), "l"(b), "l"(c)); return d;
}
__device__ __forceinline__ void pf_l2(const void* p) {
    asm volatile("prefetch.global.L2 [%0];" :: "l"(p));
}
// streaming (evict-first) output store: keeps L2 for the gather tables
__device__ __forceinline__ void stg_cs4(float* p, float4 v) {
    asm volatile("st.global.cs.v4.f32 [%0], {%1, %2, %3, %4};"
                 :: "l"(p), "f"(v.x), "f"(v.y), "f"(v.z), "f"(v.w) : "memory");
}

// smem layout (shared by both GEMM kernels)
constexpr int OF_BS  = 0;                 // 64*128 floats  = 32 KB
constexpr int OF_AT0 = 32768;             // 32*128 floats  = 16 KB
constexpr int OF_AT1 = 49152;             // 16 KB
constexpr int OF_AU  = 65536;             // 128 ints
constexpr int OF_AI  = 66048;             // 128 ints
constexpr int SMEM_DYN = 66560;

// ---------------- core tile body (shared) ----------------
// Computes acc for tile rows [row0, row0+128) with B from g_Wp[koff:+64,:].
// 256 thr; warp w: rows (w&1)*64, cols (w>>1)*32; thread 8x8 in f32x2.
__device__ __forceinline__ void gemm_tile(const float* __restrict__ A, int M,
                                          int row0, int koff, char* smem,
                                          int t, int row_w, int ty, int c0,
                                          ull acc[8][4]) {
    float* Bs = (float*)(smem + OF_BS);
    const float4* A4 = (const float4*)A;

    // issue chunk-0 A loads first (longest latency)
    float4 v[4];
#pragma unroll
    for (int it = 0; it < 4; it++) {
        int q = it * 256 + t;
        int gr = min(row0 + (q >> 3), M - 1);
        v[it] = A4[(size_t)gr * 16 + (q & 7)];
    }
    // stage B (straight copy 64x128, L2-hot)
    {
        const float4* w4 = (const float4*)(g_Wp + koff * 128);
        float4* b4 = (float4*)Bs;
#pragma unroll
        for (int i = 0; i < 8; i++) b4[i * 256 + t] = w4[i * 256 + t];
    }
    // store chunk 0 into At0 (swizzled transpose)
    float* At = (float*)(smem + OF_AT0);
#pragma unroll
    for (int it = 0; it < 4; it++) {
        int q = it * 256 + t;
        int r = q >> 3, kc4 = q & 7;
        int pr = r ^ (4 * kc4);
        float* dst = At + (kc4 * 4) * 128 + pr;
        dst[0] = v[it].x; dst[128] = v[it].y; dst[256] = v[it].z; dst[384] = v[it].w;
    }
    __syncthreads();

    // issue chunk-1 A loads (hidden behind chunk-0 compute)
#pragma unroll
    for (int it = 0; it < 4; it++) {
        int q = it * 256 + t;
        int gr = min(row0 + (q >> 3), M - 1);
        v[it] = A4[(size_t)gr * 16 + 8 + (q & 7)];
    }

#pragma unroll
    for (int i = 0; i < 8; i++)
#pragma unroll
        for (int j = 0; j < 4; j++) acc[i][j] = 0ull;

    // compute chunk 0
#pragma unroll 4
    for (int kk = 0; kk < 32; kk++) {
        int vv = kk & 28;
        const float* pa = At + kk * 128 + row_w + ((4 * ty) ^ vv);
        float4 a0 = *(const float4*)pa;
        float4 a1 = *(const float4*)(pa + 32);
        const float* pb = Bs + kk * 128 + c0;
        ulonglong2 bA = *(const ulonglong2*)(pb);
        ulonglong2 bB = *(const ulonglong2*)(pb + 4);
#pragma unroll
        for (int i = 0; i < 8; i++) {
            float av = (i == 0) ? a0.x : (i == 1) ? a0.y : (i == 2) ? a0.z
                     : (i == 3) ? a0.w : (i == 4) ? a1.x : (i == 5) ? a1.y
                     : (i == 6) ? a1.z : a1.w;
            ull ad = pk2(av, av);
            acc[i][0] = fma2_(ad, bA.x, acc[i][0]);
            acc[i][1] = fma2_(ad, bA.y, acc[i][1]);
            acc[i][2] = fma2_(ad, bB.x, acc[i][2]);
            acc[i][3] = fma2_(ad, bB.y, acc[i][3]);
        }
    }

    // store chunk 1 into At1
    float* At1 = (float*)(smem + OF_AT1);
#pragma unroll
    for (int it = 0; it < 4; it++) {
        int q = it * 256 + t;
        int r = q >> 3, kc4 = q & 7;
        int pr = r ^ (4 * kc4);
        float* dst = At1 + (kc4 * 4) * 128 + pr;
        dst[0] = v[it].x; dst[128] = v[it].y; dst[256] = v[it].z; dst[384] = v[it].w;
    }
    __syncthreads();

    // compute chunk 1
#pragma unroll 4
    for (int kk = 0; kk < 32; kk++) {
        int vv = kk & 28;
        const float* pa = At1 + kk * 128 + row_w + ((4 * ty) ^ vv);
        float4 a0 = *(const float4*)pa;
        float4 a1 = *(const float4*)(pa + 32);
        const float* pb = Bs + (32 + kk) * 128 + c0;
        ulonglong2 bA = *(const ulonglong2*)(pb);
        ulonglong2 bB = *(const ulonglong2*)(pb + 4);
#pragma unroll
        for (int i = 0; i < 8; i++) {
            float av = (i == 0) ? a0.x : (i == 1) ? a0.y : (i == 2) ? a0.z
                     : (i == 3) ? a0.w : (i == 4) ? a1.x : (i == 5) ? a1.y
                     : (i == 6) ? a1.z : a1.w;
            ull ad = pk2(av, av);
            acc[i][0] = fma2_(ad, bA.x, acc[i][0]);
            acc[i][1] = fma2_(ad, bA.y, acc[i][1]);
            acc[i][2] = fma2_(ad, bB.x, acc[i][2]);
            acc[i][3] = fma2_(ad, bB.y, acc[i][3]);
        }
    }
}

// ---------------- fused table builder: item blocks then user blocks ----------------
__global__ __launch_bounds__(256, 2)
void k_tables(const float* __restrict__ item, int n_i, int nbi,
              const float* __restrict__ user, int n_u) {
    extern __shared__ __align__(16) char smem[];
    const int t = threadIdx.x;
    const int w = t >> 5, l = t & 31;
    const int tx = l & 3, ty = l >> 2;
    const int row_w = (w & 1) * 64;
    const int c0 = (w >> 1) * 32 + tx * 8;
    const int rA = row_w + 4 * ty;

    const bool is_item = (int)blockIdx.x < nbi;
    const float* A = is_item ? item : user;
    const int M = is_item ? n_i : n_u;
    const int row0 = (is_item ? blockIdx.x : blockIdx.x - nbi) * 128;
    const int koff = is_item ? 128 : 64;
    __half* T = is_item ? g_Ti : g_Tu;

    ull acc[8][4];
    gemm_tile(A, M, row0, koff, smem, t, row_w, ty, c0, acc);

#pragma unroll
    for (int i = 0; i < 8; i++) {
        int lr = rA + (i & 3) + (i >> 2) * 32;
        int gr = row0 + lr;
        if (gr >= M) continue;
        float2 p0 = upk2(acc[i][0]), p1 = upk2(acc[i][1]);
        float2 p2 = upk2(acc[i][2]), p3 = upk2(acc[i][3]);
        __half2 h0 = __float22half2_rn(p0);
        __half2 h1 = __float22half2_rn(p1);
        __half2 h2 = __float22half2_rn(p2);
        __half2 h3 = __float22half2_rn(p3);
        uint4 pk;
        pk.x = *(unsigned*)&h0; pk.y = *(unsigned*)&h1;
        pk.z = *(unsigned*)&h2; pk.w = *(unsigned*)&h3;
        *(uint4*)(T + ((size_t)gr << 7) + c0) = pk;
    }
}

// ---------------- review GEMM + gather + relu ----------------
__global__ __launch_bounds__(256, 2)
void k_review(const float* __restrict__ A, int M, float* __restrict__ Cout,
              const void* __restrict__ adjA, const void* __restrict__ adjB) {
    extern __shared__ __align__(16) char smem[];
    int* s_au = (int*)(smem + OF_AU);
    int* s_ai = (int*)(smem + OF_AI);

    const int t = threadIdx.x;
    const int w = t >> 5, l = t & 31;
    const int tx = l & 3, ty = l >> 2;
    const int row_w = (w & 1) * 64;
    const int c0 = (w >> 1) * 32 + tx * 8;
    const int row0 = blockIdx.x * 128;
    const int rA = row_w + 4 * ty;

    // adjacency indices + L2 prefetch (before the long compute)
    {
        int lr = t & 127;
        int gr = min(row0 + lr, M - 1);
        if (t < 128) {
            const void* aU = g_swap ? adjB : adjA;
            int iu = g_is64 ? (int)((const long long*)aU)[gr] : ((const int*)aU)[gr];
            s_au[lr] = iu;
            const char* p = (const char*)(g_Tu + ((size_t)iu << 7));
            pf_l2(p); pf_l2(p + 128);
        } else {
            const void* aI = g_swap ? adjA : adjB;
            int ii = g_is64 ? (int)((const long long*)aI)[gr] : ((const int*)aI)[gr];
            s_ai[lr] = ii;
            const char* p = (const char*)(g_Ti + ((size_t)ii << 7));
            pf_l2(p); pf_l2(p + 128);
        }
    }

    ull acc[8][4];
    gemm_tile(A, M, row0, 0, smem, t, row_w, ty, c0, acc);

    // ---- epilogue: two halves of 4 rows; batch all 8 gather LDGs per half ----
#pragma unroll
    for (int h = 0; h < 2; h++) {
        uint4 gu[4], gi[4];
#pragma unroll
        for (int i = 0; i < 4; i++) {
            int lr = rA + i + h * 32;
            gu[i] = __ldg((const uint4*)(g_Tu + ((size_t)s_au[lr] << 7) + c0));
            gi[i] = __ldg((const uint4*)(g_Ti + ((size_t)s_ai[lr] << 7) + c0));
        }
#pragma unroll
        for (int i = 0; i < 4; i++) {
            int a = h * 4 + i;
            int gr = row0 + rA + i + h * 32;
            if (gr >= M) continue;
            float2 p0 = upk2(acc[a][0]), p1 = upk2(acc[a][1]);
            float2 p2 = upk2(acc[a][2]), p3 = upk2(acc[a][3]);
            float2 u0 = __half22float2(*(__half2*)&gu[i].x);
            float2 u1 = __half22float2(*(__half2*)&gu[i].y);
            float2 u2 = __half22float2(*(__half2*)&gu[i].z);
            float2 u3 = __half22float2(*(__half2*)&gu[i].w);
            float2 w0 = __half22float2(*(__half2*)&gi[i].x);
            float2 w1 = __half22float2(*(__half2*)&gi[i].y);
            float2 w2 = __half22float2(*(__half2*)&gi[i].z);
            float2 w3 = __half22float2(*(__half2*)&gi[i].w);
            float4 o0, o1;
            o0.x = fmaxf(p0.x + u0.x + w0.x, 0.f);
            o0.y = fmaxf(p0.y + u0.y + w0.y, 0.f);
            o0.z = fmaxf(p1.x + u1.x + w1.x, 0.f);
            o0.w = fmaxf(p1.y + u1.y + w1.y, 0.f);
            o1.x = fmaxf(p2.x + u2.x + w2.x, 0.f);
            o1.y = fmaxf(p2.y + u2.y + w2.y, 0.f);
            o1.z = fmaxf(p3.x + u3.x + w3.x, 0.f);
            o1.w = fmaxf(p3.y + u3.y + w3.y, 0.f);
            float* dst = Cout + ((size_t)gr << 7) + c0;
            stg_cs4(dst, o0);
            stg_cs4(dst + 4, o1);
        }
    }
}

// ---------------- launch ----------------
extern "C" void kernel_launch(void* const* d_in, const int* in_sizes, int n_in,
                              void* d_out, int out_size) {
    // classify inputs by element count (robust to metadata ordering)
    const float *review = nullptr, *user = nullptr, *item = nullptr, *W = nullptr;
    const void *adjA = nullptr, *adjB = nullptr;
    int n_r = 1000000, n_u = 500000, n_i = 100000;
    for (int k = 0; k < n_in; k++) {
        long long sz = in_sizes[k];
        if (sz == 64000000)      { review = (const float*)d_in[k]; n_r = (int)(sz / 64); }
        else if (sz == 32000000) { user   = (const float*)d_in[k]; n_u = (int)(sz / 64); }
        else if (sz == 6400000)  { item   = (const float*)d_in[k]; n_i = (int)(sz / 64); }
        else if (sz == 24576)    { W      = (const float*)d_in[k]; }
        else if (!adjA)          { adjA   = d_in[k]; }
        else                     { adjB   = d_in[k]; }
    }
    if (!review || !user || !item || !W || !adjA || !adjB) {
        review = (const float*)d_in[0]; user = (const float*)d_in[1];
        item   = (const float*)d_in[2]; W    = (const float*)d_in[3];
        adjA   = d_in[4];               adjB = d_in[5];
        n_r = in_sizes[0] / 64; n_u = in_sizes[1] / 64; n_i = in_sizes[2] / 64;
    }
    float* out = (float*)d_out;

    cudaFuncSetAttribute(k_tables, cudaFuncAttributeMaxDynamicSharedMemorySize, SMEM_DYN);
    cudaFuncSetAttribute(k_review, cudaFuncAttributeMaxDynamicSharedMemorySize, SMEM_DYN);

    int nbi = (n_i + 127) / 128;
    int nbu = (n_u + 127) / 128;
    k_build_wp<<<1, 1024>>>(W, adjA);
    k_tables<<<nbi + nbu, 256, SMEM_DYN>>>(item, n_i, nbi, user, n_u);
    k_review<<<(n_r + 127) / 128, 256, SMEM_DYN>>>(review, n_r, out, adjA, adjB);
}